// round 10
// baseline (speedup 1.0000x reference)
#include <cuda_runtime.h>
#include <cuda_bf16.h>

// wACSFRad R10: SINGLE fused persistent kernel with software global barriers.
//  phase A: pack xyzw=(x,y,z,float(type)), zero cursors  (table staged alongside)
//  phase B: scatter: cull r2>=64 (fc==0, ~57% of edges) & s==0;
//           bucket[recv*CAP + atomicAdd(cursor)] = (rij, s)
//  phase C: compute: 4 lanes/node, strided (~5.3 nodes/group); float4 bucket
//           reads; exp arg as quadratic form A*r^2+B*r+C (3 FMA/param/edge);
//           ex2.approx; plain coalesced stores; in-kernel overflow fold-in.
// Barriers: monotonic counters, acquire-spin + nanosleep; replay-safe resets
// (bar2 reset pre-bar1 by CTA0; bar1 reset post-bar2).
// Co-residency: grid=296 = 2 CTAs/SM (launch_bounds(256,2), 20.8KB smem).
//
// Inputs: z i32[100000], xyz f32[100000,3], eij i32[3200000,2], eta_mu f32[118,22,2]
// Output: f32 [100000,22]

#define N_NODES_MAX 100000
#define N_TYPES 118
#define N_PARAMS 22
#define CAP 64                   // surviving degree ~Poisson(13.8), max≈40
#define OVF_CAP 3200000          // bulletproof: can hold every edge
#define PI_OVER_CUT 0.39269908169872414f
#define LOG2E 1.4426950408889634f
#define GRID 296
#define TPB 256

__device__ float4 g_xyzw[N_NODES_MAX];
__device__ int    g_cursor[N_NODES_MAX];
__device__ __align__(16) float2 g_bucket[(long long)N_NODES_MAX * CAP]; // (rij,s)
__device__ int    g_ovf_count;
__device__ int    g_ovf_recv[OVF_CAP];
__device__ float2 g_ovf_rs[OVF_CAP];
__device__ unsigned g_bar1, g_bar2;   // zero-initialized at module load

__device__ __forceinline__ float ex2f(float x) {
    float r;
    asm("ex2.approx.f32 %0, %1;" : "=f"(r) : "f"(x));
    return r;
}

// Global barrier: CTA-arrive (tid0) + acquire-spin. Counter is NOT reset here;
// caller handles replay-safe resets.
__device__ __forceinline__ void grid_barrier(unsigned* cnt, unsigned target) {
    __syncthreads();
    if (threadIdx.x == 0) {
        __threadfence();                       // release prior writes
        atomicAdd(cnt, 1u);
        unsigned v;
        do {
            asm volatile("ld.acquire.gpu.u32 %0, [%1];"
                         : "=r"(v) : "l"(cnt) : "memory");
            if (v >= target) break;
            __nanosleep(64);
        } while (true);
    }
    __syncthreads();
}

__device__ __forceinline__ void scatter_one(int recv, int send) {
    const float4 a = __ldg(&g_xyzw[recv]);
    const float4 b = __ldg(&g_xyzw[send]);
    const float dx = a.x - b.x, dy = a.y - b.y, dz = a.z - b.z;
    const float r2 = fmaf(dx, dx, fmaf(dy, dy, dz * dz));
    if (r2 >= 64.0f) return;                   // fc == 0: dead edge
    const float rij = sqrtf(r2);
    const float s = 0.5f * (__cosf(rij * PI_OVER_CUT) + 1.0f) * b.w;
    if (s == 0.0f) return;                     // w == 0 senders

    const int pos = atomicAdd(&g_cursor[recv], 1);
    if (pos < CAP) {
        g_bucket[(long long)recv * CAP + pos] = make_float2(rij, s);
    } else {                                   // never at these degrees
        const int o = atomicAdd(&g_ovf_count, 1);
        if (o < OVF_CAP) {
            g_ovf_recv[o] = recv;
            g_ovf_rs[o] = make_float2(rij, s);
        }
    }
}

__global__ void __launch_bounds__(TPB, 2) wacsf_fused_kernel(
    const int*    __restrict__ z,
    const float*  __restrict__ xyz,
    const int4*   __restrict__ eij2,
    const int2*   __restrict__ eij,
    const float2* __restrict__ eta_mu2,
    float*        __restrict__ out,
    int n_nodes, int n_edges)
{
    __shared__ float2 tbl[N_TYPES * N_PARAMS];   // (e2 = -eta*log2e, mu)
    const int tid = threadIdx.x;
    const int gtid = blockIdx.x * TPB + tid;
    const int nthreads = gridDim.x * TPB;

    // stage table (no dependency on any phase)
    for (int i = tid; i < N_TYPES * N_PARAMS; i += TPB) {
        const float2 p = eta_mu2[i];
        tbl[i] = make_float2(-p.x * LOG2E, p.y);
    }

    // ---- phase A: pack nodes, zero cursors ----
    const int n4 = n_nodes >> 2;
    const float4* xyz4 = (const float4*)xyz;
    const int4*   z4   = (const int4*)z;
    for (int i = gtid; i < n4; i += nthreads) {
        const float4 a = __ldg(&xyz4[3 * i + 0]);
        const float4 b = __ldg(&xyz4[3 * i + 1]);
        const float4 c = __ldg(&xyz4[3 * i + 2]);
        const int4  zz = __ldg(&z4[i]);
        g_xyzw[4 * i + 0] = make_float4(a.x, a.y, a.z, (float)zz.x);
        g_xyzw[4 * i + 1] = make_float4(a.w, b.x, b.y, (float)zz.y);
        g_xyzw[4 * i + 2] = make_float4(b.z, b.w, c.x, (float)zz.z);
        g_xyzw[4 * i + 3] = make_float4(c.y, c.z, c.w, (float)zz.w);
        *reinterpret_cast<int4*>(&g_cursor[4 * i]) = make_int4(0, 0, 0, 0);
    }
    if (gtid == 0) {
        for (int i = n4 * 4; i < n_nodes; i++) {       // generic tail
            g_xyzw[i] = make_float4(xyz[3 * i], xyz[3 * i + 1],
                                    xyz[3 * i + 2], (float)z[i]);
            g_cursor[i] = 0;
        }
        g_ovf_count = 0;
        // Replay-safe: reset bar2 BEFORE arriving at bar1. Every other CTA
        // touches bar2 only after bar1 releases, which happens-after this.
        atomicExch(&g_bar2, 0u);
    }
    grid_barrier(&g_bar1, gridDim.x);

    // ---- phase B: scatter with dead-edge culling ----
    const int n_pairs = n_edges >> 1;
    for (int i = gtid; i < n_pairs; i += nthreads) {
        const int4 v = __ldg(&eij2[i]);
        scatter_one(v.x, v.y);
        scatter_one(v.z, v.w);
    }
    if (gtid == 0 && (n_edges & 1)) {
        const int2 t = __ldg(&eij[n_edges - 1]);
        scatter_one(t.x, t.y);
    }
    grid_barrier(&g_bar2, gridDim.x);
    if (gtid == 0) atomicExch(&g_bar1, 0u);   // all CTAs provably past bar1

    // ---- phase C: per-node accumulate, 4 lanes/node, strided ----
    const int ngroups = nthreads >> 2;
    const int grp0 = gtid >> 2;
    const int r = gtid & 3;

    for (int node = grp0; node < n_nodes; node += ngroups) {
        const float4 a = __ldg(&g_xyzw[node]);
        const int t = (int)a.w;
        const int deg_raw = g_cursor[node];
        const int deg = deg_raw < CAP ? deg_raw : CAP;
        const float4* __restrict__ bkt4 =
            reinterpret_cast<const float4*>(g_bucket + (long long)node * CAP);

        // lane r owns params k = r, r+4, ...; quadratic form:
        // e2*(x-mu)^2 = A*x^2 + B*x + C
        float A[6], B[6], C[6], acc[6];
        #pragma unroll
        for (int j = 0; j < 6; j++) {
            const int k = r + 4 * j;
            const int kk = k < N_PARAMS ? k : (N_PARAMS - 1);
            const float2 p = tbl[t * N_PARAMS + kk];
            A[j] = p.x;
            B[j] = -2.0f * p.x * p.y;
            C[j] = p.x * p.y * p.y;
            acc[j] = 0.0f;
        }

        const int npair = deg >> 1;
        #pragma unroll 2
        for (int p = 0; p < npair; p++) {
            const float4 v = __ldg(&bkt4[p]);      // (r1, s1, r2, s2)
            const float q1 = v.x * v.x;
            const float q2 = v.z * v.z;
            #pragma unroll
            for (int q = 0; q < 6; q++) {
                acc[q] = fmaf(v.y,
                    ex2f(fmaf(A[q], q1, fmaf(B[q], v.x, C[q]))), acc[q]);
                acc[q] = fmaf(v.w,
                    ex2f(fmaf(A[q], q2, fmaf(B[q], v.z, C[q]))), acc[q]);
            }
        }
        if (deg & 1) {
            const float2 rs =
                __ldg(&reinterpret_cast<const float2*>(bkt4)[deg - 1]);
            const float q1 = rs.x * rs.x;
            #pragma unroll
            for (int q = 0; q < 6; q++) {
                acc[q] = fmaf(rs.y,
                    ex2f(fmaf(A[q], q1, fmaf(B[q], rs.x, C[q]))), acc[q]);
            }
        }

        // CAP-overflow fold-in (never taken; node-local, no atomics)
        if (deg_raw > CAP) {
            int count = g_ovf_count;
            if (count > OVF_CAP) count = OVF_CAP;
            for (int i = 0; i < count; i++) {
                if (g_ovf_recv[i] == node) {
                    const float2 rs = g_ovf_rs[i];
                    const float q1 = rs.x * rs.x;
                    #pragma unroll
                    for (int q = 0; q < 6; q++) {
                        acc[q] = fmaf(rs.y,
                            ex2f(fmaf(A[q], q1, fmaf(B[q], rs.x, C[q]))), acc[q]);
                    }
                }
            }
        }

        float* o = out + (long long)node * N_PARAMS;
        #pragma unroll
        for (int j = 0; j < 6; j++) {
            const int k = r + 4 * j;
            if (k < N_PARAMS) o[k] = acc[j];       // plain coalesced store
        }
    }
}

extern "C" void kernel_launch(void* const* d_in, const int* in_sizes, int n_in,
                              void* d_out, int out_size) {
    const int*    z       = (const int*)   d_in[0];
    const float*  xyz     = (const float*) d_in[1];
    const int2*   eij     = (const int2*)  d_in[2];
    const int4*   eij2    = (const int4*)  d_in[2];
    const float2* eta_mu2 = (const float2*)d_in[3];
    float*        out     = (float*)d_out;

    const int n_nodes = in_sizes[0];
    const int n_edges = in_sizes[2] / 2;

    wacsf_fused_kernel<<<GRID, TPB>>>(z, xyz, eij2, eij, eta_mu2, out,
                                      n_nodes, n_edges);
}

// round 11
// speedup vs baseline: 1.7405x; 1.7405x over previous
#include <cuda_runtime.h>
#include <cuda_bf16.h>

// wACSFRad R11: R9 structure (3 kernels — fused persistent R10 regressed 73%:
// scatter needs full occupancy for gather-latency hiding) + batched scatter
// gathers (all 4 endpoint loads issued before any branch/atomic -> 2x MLP on
// the critical chain).
//  pack:    4 nodes/thread vectorized; xyzw=(x,y,z,float(type)); cursor=0
//  scatter: 2 edges/thread, BATCHED loads; cull r2>=64 (fc==0, ~57% of edges)
//           and s==0; bucket[recv*CAP + atomicAdd(cursor)] = (rij, s)
//  compute: 4 lanes/node; float4 bucket reads (2 edges/LDG, group-broadcast);
//           accurate exp form e2*(r-mu)^2 via ex2.approx (NOT the quadratic
//           form — R10 showed 10x rel_err loss); plain coalesced stores;
//           in-kernel overflow fold-in (never taken, correctness guard).
//
// Inputs: z i32[100000], xyz f32[100000,3], eij i32[3200000,2], eta_mu f32[118,22,2]
// Output: f32 [100000,22]

#define N_NODES_MAX 100000
#define N_TYPES 118
#define N_PARAMS 22
#define CAP 64                   // surviving degree ~Poisson(13.8), max≈40
#define OVF_CAP 3200000          // bulletproof: can hold every edge
#define PI_OVER_CUT 0.39269908169872414f
#define LOG2E 1.4426950408889634f

__device__ float4 g_xyzw[N_NODES_MAX];
__device__ int    g_cursor[N_NODES_MAX];
__device__ __align__(16) float2 g_bucket[(long long)N_NODES_MAX * CAP]; // (rij,s)
__device__ int    g_ovf_count;
__device__ int    g_ovf_recv[OVF_CAP];
__device__ float2 g_ovf_rs[OVF_CAP];

__device__ __forceinline__ float ex2f(float x) {
    float r;
    asm("ex2.approx.f32 %0, %1;" : "=f"(r) : "f"(x));
    return r;
}

__global__ void pack_nodes_kernel(const int4* __restrict__ z4,
                                  const float4* __restrict__ xyz4, int n4) {
    const int i = blockIdx.x * blockDim.x + threadIdx.x;   // group of 4 nodes
    if (i < n4) {
        const float4 a = __ldg(&xyz4[3 * i + 0]);
        const float4 b = __ldg(&xyz4[3 * i + 1]);
        const float4 c = __ldg(&xyz4[3 * i + 2]);
        const int4  zz = __ldg(&z4[i]);
        g_xyzw[4 * i + 0] = make_float4(a.x, a.y, a.z, (float)zz.x);
        g_xyzw[4 * i + 1] = make_float4(a.w, b.x, b.y, (float)zz.y);
        g_xyzw[4 * i + 2] = make_float4(b.z, b.w, c.x, (float)zz.z);
        g_xyzw[4 * i + 3] = make_float4(c.y, c.z, c.w, (float)zz.w);
        *reinterpret_cast<int4*>(&g_cursor[4 * i]) = make_int4(0, 0, 0, 0);
    }
    if (i == 0) g_ovf_count = 0;
}

// Post-gather tail: cull, compute (rij,s), claim slot, store.
__device__ __forceinline__ void scatter_tail(int recv, float4 a, float4 b) {
    const float dx = a.x - b.x, dy = a.y - b.y, dz = a.z - b.z;
    const float r2 = fmaf(dx, dx, fmaf(dy, dy, dz * dz));
    if (r2 >= 64.0f) return;                   // fc == 0: dead edge
    const float rij = sqrtf(r2);
    const float s = 0.5f * (__cosf(rij * PI_OVER_CUT) + 1.0f) * b.w;
    if (s == 0.0f) return;                     // w == 0 senders

    const int pos = atomicAdd(&g_cursor[recv], 1);
    if (pos < CAP) {
        g_bucket[(long long)recv * CAP + pos] = make_float2(rij, s);
    } else {                                   // never at these degrees
        const int o = atomicAdd(&g_ovf_count, 1);
        if (o < OVF_CAP) {
            g_ovf_recv[o] = recv;
            g_ovf_rs[o] = make_float2(rij, s);
        }
    }
}

__global__ void __launch_bounds__(256) scatter_kernel(
    const int4* __restrict__ eij2,        // 2 edges per int4
    const int2* __restrict__ eij,
    int n_pairs, int n_edges)
{
    const int i = blockIdx.x * blockDim.x + threadIdx.x;
    if (i < n_pairs) {
        const int4 v = __ldg(&eij2[i]);
        // BATCH all 4 gathers before any branch/atomic: 4 chains in flight
        const float4 a0 = __ldg(&g_xyzw[v.x]);
        const float4 b0 = __ldg(&g_xyzw[v.y]);
        const float4 a1 = __ldg(&g_xyzw[v.z]);
        const float4 b1 = __ldg(&g_xyzw[v.w]);
        scatter_tail(v.x, a0, b0);
        scatter_tail(v.z, a1, b1);
    }
    if (i == 0 && (n_edges & 1)) {
        const int2 t = __ldg(&eij[n_edges - 1]);
        const float4 a = __ldg(&g_xyzw[t.x]);
        const float4 b = __ldg(&g_xyzw[t.y]);
        scatter_tail(t.x, a, b);
    }
}

__global__ void __launch_bounds__(256) compute_kernel(
    const float2* __restrict__ eta_mu2,
    float* __restrict__ out,
    int n_nodes)
{
    // staged table, eta prescaled: (e2 = -eta*log2e, mu). 20768 B
    __shared__ float2 tbl[N_TYPES * N_PARAMS];
    for (int i = threadIdx.x; i < N_TYPES * N_PARAMS; i += blockDim.x) {
        const float2 p = eta_mu2[i];
        tbl[i] = make_float2(-p.x * LOG2E, p.y);
    }
    __syncthreads();

    const int gid = blockIdx.x * blockDim.x + threadIdx.x;
    int node = gid >> 2;
    const int r = gid & 3;
    if (node >= n_nodes) node = n_nodes - 1;       // benign duplicate work

    const float4 a = __ldg(&g_xyzw[node]);
    const int t = (int)a.w;
    const int deg_raw = g_cursor[node];
    const int deg = deg_raw < CAP ? deg_raw : CAP;
    const float4* __restrict__ bkt4 =
        reinterpret_cast<const float4*>(g_bucket + (long long)node * CAP);

    // lane r owns params k = r, r+4, ... (6 slots; 2 padded in lanes 2,3)
    float e2[6], mu[6];
    #pragma unroll
    for (int j = 0; j < 6; j++) {
        const int k = r + 4 * j;
        const int kk = k < N_PARAMS ? k : (N_PARAMS - 1);
        const float2 p = tbl[t * N_PARAMS + kk];
        e2[j] = p.x; mu[j] = p.y;
    }
    float acc[6] = {0.f, 0.f, 0.f, 0.f, 0.f, 0.f};

    const int npair = deg >> 1;
    #pragma unroll 2
    for (int p = 0; p < npair; p++) {
        const float4 v = __ldg(&bkt4[p]);          // (r1, s1, r2, s2)
        #pragma unroll
        for (int q = 0; q < 6; q++) {
            const float d1 = v.x - mu[q];
            const float d2 = v.z - mu[q];
            acc[q] = fmaf(v.y, ex2f((e2[q] * d1) * d1), acc[q]);
            acc[q] = fmaf(v.w, ex2f((e2[q] * d2) * d2), acc[q]);
        }
    }
    if (deg & 1) {
        const float2 rs =
            __ldg(&reinterpret_cast<const float2*>(bkt4)[deg - 1]);
        #pragma unroll
        for (int q = 0; q < 6; q++) {
            const float d = rs.x - mu[q];
            acc[q] = fmaf(rs.y, ex2f((e2[q] * d) * d), acc[q]);
        }
    }

    // CAP-overflow fold-in (never taken at these degrees; node-local)
    if (deg_raw > CAP) {
        int count = g_ovf_count;
        if (count > OVF_CAP) count = OVF_CAP;
        for (int i = 0; i < count; i++) {
            if (g_ovf_recv[i] == node) {
                const float2 rs = g_ovf_rs[i];
                #pragma unroll
                for (int q = 0; q < 6; q++) {
                    const float d = rs.x - mu[q];
                    acc[q] = fmaf(rs.y, ex2f((e2[q] * d) * d), acc[q]);
                }
            }
        }
    }

    float* o = out + (long long)node * N_PARAMS;
    #pragma unroll
    for (int j = 0; j < 6; j++) {
        const int k = r + 4 * j;
        if (k < N_PARAMS) o[k] = acc[j];           // plain coalesced store
    }
}

extern "C" void kernel_launch(void* const* d_in, const int* in_sizes, int n_in,
                              void* d_out, int out_size) {
    const int4*   z4      = (const int4*)  d_in[0];
    const float4* xyz4    = (const float4*)d_in[1];
    const int2*   eij     = (const int2*)  d_in[2];
    const int4*   eij2    = (const int4*)  d_in[2];
    const float2* eta_mu2 = (const float2*)d_in[3];
    float*        out     = (float*)d_out;

    const int n_nodes = in_sizes[0];        // 100000, divisible by 4
    const int n4 = n_nodes / 4;
    const int n_edges = in_sizes[2] / 2;
    const int n_pairs = n_edges / 2;

    pack_nodes_kernel<<<(n4 + 255) / 256, 256>>>(z4, xyz4, n4);
    scatter_kernel<<<(n_pairs + 255) / 256, 256>>>(eij2, eij, n_pairs, n_edges);

    const int threads_needed = n_nodes * 4;
    compute_kernel<<<(threads_needed + 255) / 256, 256>>>(eta_mu2, out, n_nodes);
}